// round 1
// baseline (speedup 1.0000x reference)
#include <cuda_runtime.h>
#include <math.h>

#define BB 8
#define CC 256
#define HH 128
#define WW 128
#define NN (HH*WW)          // 16384
#define NPOS 256
#define NHARD 96
#define NRAND 32
#define TEMP_INV (1.0f/0.07f)

// ---------------- scratch (static device globals; no allocation) ------------
__device__ float g_rgbT[BB*NN*CC];      // normalized rgb, [b][pixel][channel]
__device__ float g_pos[BB*NN];
__device__ float g_lse[BB*NN];
__device__ float g_maxneg[BB*NN];
__device__ float g_lse_hard[BB*NPOS];
__device__ float g_max_hard[BB*NPOS];
__device__ float g_acc[3];              // loss_sum, mask_sum, correct_sum

// ---------------- kernel 0: zero accumulators --------------------------------
__global__ void k_init() {
    if (threadIdx.x < 3) g_acc[threadIdx.x] = 0.0f;
}

// ---------------- kernel 1: normalize + transpose rgb -> g_rgbT --------------
// block = 256 threads handles 32 pixels (contiguous along W) of one batch.
__global__ __launch_bounds__(256) void k_norm_t(const float* __restrict__ in) {
    __shared__ float s_tile[CC*33];
    __shared__ float s_red[8*33];
    __shared__ float s_inv[32];
    const int tid = threadIdx.x;
    const int tx = tid & 31;        // pixel in tile
    const int ty = tid >> 5;        // channel group
    const int blocksPerBatch = NN/32;
    const int b  = blockIdx.x / blocksPerBatch;
    const int n0 = (blockIdx.x % blocksPerBatch) * 32;

    const float* src = in + b*CC*NN + n0;
    #pragma unroll
    for (int i = 0; i < 32; i++) {
        int c = i*8 + ty;
        s_tile[c*33 + tx] = src[c*NN + tx];      // coalesced 128B
    }
    __syncthreads();

    float ss = 0.0f;
    #pragma unroll
    for (int j = 0; j < 32; j++) {
        float v = s_tile[(ty*32 + j)*33 + tx];
        ss += v*v;
    }
    s_red[ty*33 + tx] = ss;
    __syncthreads();
    if (ty == 0) {
        float t = 0.0f;
        #pragma unroll
        for (int j = 0; j < 8; j++) t += s_red[j*33 + tx];
        s_inv[tx] = 1.0f / fmaxf(sqrtf(t), 1e-12f);
    }
    __syncthreads();

    // write transposed+normalized rows: 64 threads per pixel (float4)
    float* dst = g_rgbT + (b*NN + n0)*CC;
    const int cb = tid & 63;
    const int pq = tid >> 6;
    #pragma unroll
    for (int it = 0; it < 8; it++) {
        int px = it*4 + pq;
        float inv = s_inv[px];
        float4 v;
        v.x = s_tile[(cb*4+0)*33 + px] * inv;
        v.y = s_tile[(cb*4+1)*33 + px] * inv;
        v.z = s_tile[(cb*4+2)*33 + px] * inv;
        v.w = s_tile[(cb*4+3)*33 + px] * inv;
        reinterpret_cast<float4*>(dst + px*CC)[cb] = v;
    }
}

// ---------------- kernel 2: main per-pixel pass -------------------------------
// block = 256 threads = 8 warps, 32 pixels. Dynamic smem.
__device__ __forceinline__ int corner_idx(int xx, int yy, float& w) {
    bool v = (xx >= 0) & (xx < WW) & (yy >= 0) & (yy < HH);
    if (!v) w = 0.0f;
    int cx = min(max(xx, 0), WW-1);
    int cy = min(max(yy, 0), HH-1);
    return cy*WW + cx;
}

__global__ __launch_bounds__(256) void k_main(const float* __restrict__ dep,
                                              const float* __restrict__ proj,
                                              const int*   __restrict__ rand_idx) {
    extern __shared__ float sm[];
    float* s_dep  = sm;                       // 256*33
    float* s_rand = sm + CC*33;               // 32*256 (16B aligned: 8448 floats)
    float* s_sim  = s_rand + NRAND*CC;        // 32*33
    float* s_pos  = s_sim + 32*33;            // 32
    float* s_inv  = s_pos + 32;               // 32
    float* s_red  = s_inv + 32;               // 8*33

    const int tid = threadIdx.x;
    const int tx = tid & 31;
    const int ty = tid >> 5;
    const int blocksPerBatch = NN/32;
    const int b  = blockIdx.x / blocksPerBatch;
    const int n0 = (blockIdx.x % blocksPerBatch) * 32;

    // stage dep tile (coalesced)
    const float* dsrc = dep + b*CC*NN + n0;
    #pragma unroll
    for (int i = 0; i < 32; i++) {
        int c = i*8 + ty;
        s_dep[c*33 + tx] = dsrc[c*NN + tx];
    }
    // stage rand vectors (already normalized rows of g_rgbT)
    {
        int k = tid >> 3, part = tid & 7;
        int ridx = rand_idx[b*NRAND + k];
        const float4* row = reinterpret_cast<const float4*>(g_rgbT + (b*NN + ridx)*CC);
        float4* dstr = reinterpret_cast<float4*>(s_rand + k*CC);
        #pragma unroll
        for (int i = 0; i < 8; i++) dstr[part + 8*i] = row[part + 8*i];
    }
    __syncthreads();

    // depth inverse norms per pixel
    float ss = 0.0f;
    #pragma unroll
    for (int j = 0; j < 32; j++) {
        float v = s_dep[(ty*32 + j)*33 + tx];
        ss += v*v;
    }
    s_red[ty*33 + tx] = ss;
    __syncthreads();
    if (ty == 0) {
        float t = 0.0f;
        #pragma unroll
        for (int j = 0; j < 8; j++) t += s_red[j*33 + tx];
        s_inv[tx] = 1.0f / fmaxf(sqrtf(t), 1e-12f);
    }
    __syncthreads();

    // ---- phase 2: pos_sim (warp per pixel, 4 pixels per warp) ----
    const float* projU = proj + b*2*NN;
    const float* projV = projU + NN;
    for (int q = 0; q < 4; q++) {
        int px = ty*4 + q;
        int n  = n0 + px;
        float pu = projU[n], pv = projV[n];
        float x0f = floorf(pu), y0f = floorf(pv);
        float wx = pu - x0f, wy = pv - y0f;
        int x0 = (int)x0f, y0 = (int)y0f;
        float w00 = (1.0f-wx)*(1.0f-wy), w10 = wx*(1.0f-wy);
        float w01 = (1.0f-wx)*wy,        w11 = wx*wy;
        int i00 = corner_idx(x0,   y0,   w00);
        int i10 = corner_idx(x0+1, y0,   w10);
        int i01 = corner_idx(x0,   y0+1, w01);
        int i11 = corner_idx(x0+1, y0+1, w11);
        const float* r00 = g_rgbT + (b*NN + i00)*CC;
        const float* r10 = g_rgbT + (b*NN + i10)*CC;
        const float* r01 = g_rgbT + (b*NN + i01)*CC;
        const float* r11 = g_rgbT + (b*NN + i11)*CC;
        float pacc = 0.0f;
        #pragma unroll
        for (int jj = 0; jj < 8; jj++) {
            int c = tx + jj*32;
            float d = s_dep[c*33 + px];
            float r = w00*r00[c] + w10*r10[c] + w01*r01[c] + w11*r11[c];
            pacc += d*r;
        }
        #pragma unroll
        for (int o = 16; o; o >>= 1) pacc += __shfl_xor_sync(0xffffffffu, pacc, o);
        if (tx == 0) s_pos[px] = pacc;
    }

    // ---- phase 3: 32 rand dots (lane = pixel, warp owns 4 k's) ----
    {
        float a0 = 0.f, a1 = 0.f, a2 = 0.f, a3 = 0.f;
        const float4* rk0 = reinterpret_cast<const float4*>(s_rand + (ty*4+0)*CC);
        const float4* rk1 = reinterpret_cast<const float4*>(s_rand + (ty*4+1)*CC);
        const float4* rk2 = reinterpret_cast<const float4*>(s_rand + (ty*4+2)*CC);
        const float4* rk3 = reinterpret_cast<const float4*>(s_rand + (ty*4+3)*CC);
        #pragma unroll 8
        for (int c4 = 0; c4 < 64; c4++) {
            int c = c4*4;
            float d0 = s_dep[(c+0)*33 + tx];
            float d1 = s_dep[(c+1)*33 + tx];
            float d2 = s_dep[(c+2)*33 + tx];
            float d3 = s_dep[(c+3)*33 + tx];
            float4 r;
            r = rk0[c4]; a0 += d0*r.x; a0 += d1*r.y; a0 += d2*r.z; a0 += d3*r.w;
            r = rk1[c4]; a1 += d0*r.x; a1 += d1*r.y; a1 += d2*r.z; a1 += d3*r.w;
            r = rk2[c4]; a2 += d0*r.x; a2 += d1*r.y; a2 += d2*r.z; a2 += d3*r.w;
            r = rk3[c4]; a3 += d0*r.x; a3 += d1*r.y; a3 += d2*r.z; a3 += d3*r.w;
        }
        s_sim[(ty*4+0)*33 + tx] = a0;
        s_sim[(ty*4+1)*33 + tx] = a1;
        s_sim[(ty*4+2)*33 + tx] = a2;
        s_sim[(ty*4+3)*33 + tx] = a3;
    }
    __syncthreads();

    // ---- phase 4: per-pixel logsumexp / max (first warp) ----
    if (tid < 32) {
        int px = tid;
        int gp = b*NN + n0 + px;
        float scale = s_inv[px] * TEMP_INV;   // > 0, monotonic
        float pos = s_pos[px] * scale;
        float mraw = -1e30f;
        #pragma unroll
        for (int k = 0; k < 32; k++) mraw = fmaxf(mraw, s_sim[k*33 + px]);
        float mneg = mraw * scale;
        float m = fmaxf(pos, mneg);
        float se = expf(pos - m);
        #pragma unroll
        for (int k = 0; k < 32; k++) se += expf(s_sim[k*33 + px]*scale - m);
        g_pos[gp]    = pos;
        g_lse[gp]    = m + logf(se);
        g_maxneg[gp] = mneg;
    }
}

// ---------------- kernel 3: hard negatives at grid points --------------------
__global__ __launch_bounds__(256) void k_hard(const float* __restrict__ dep,
                                              const float* __restrict__ proj,
                                              const int*   __restrict__ offu,
                                              const int*   __restrict__ offv) {
    __shared__ float s_depv[CC];
    __shared__ float s_hsim[NHARD];
    __shared__ float s_red2[8];
    __shared__ float s_invd;
    const int tid = threadIdx.x;
    const int tx = tid & 31;
    const int ty = tid >> 5;
    const int b = blockIdx.x >> 8;
    const int p = blockIdx.x & 255;
    const int gh = (p >> 4) * 8;
    const int gw = (p & 15) * 8;
    const int ng = gh*WW + gw;

    s_depv[tid] = dep[b*CC*NN + tid*NN + ng];
    __syncthreads();
    {
        float v = s_depv[tid];
        float ss = v*v;
        #pragma unroll
        for (int o = 16; o; o >>= 1) ss += __shfl_xor_sync(0xffffffffu, ss, o);
        if (tx == 0) s_red2[ty] = ss;
    }
    __syncthreads();
    if (tid == 0) {
        float t = 0.0f;
        #pragma unroll
        for (int j = 0; j < 8; j++) t += s_red2[j];
        s_invd = 1.0f / fmaxf(sqrtf(t), 1e-12f);
    }
    __syncthreads();
    const float invd = s_invd;

    float pu = proj[b*2*NN + ng];
    float pv = proj[b*2*NN + NN + ng];
    int posu = (int)fminf(fmaxf(pu, 0.0f), (float)(WW-1));
    int posv = (int)fminf(fmaxf(pv, 0.0f), (float)(HH-1));

    for (int h = ty; h < NHARD; h += 8) {
        int ou = offu[(b*NHARD + h)*NPOS + p];
        int ov = offv[(b*NHARD + h)*NPOS + p];
        if (ou == 0 && ov == 0) ou = 1;
        int hu = min(max(posu + ou, 0), WW-1);
        int hv = min(max(posv + ov, 0), HH-1);
        const float* row = g_rgbT + (b*NN + hv*WW + hu)*CC;
        float acc = 0.0f;
        #pragma unroll
        for (int jj = 0; jj < 8; jj++) {
            int c = tx + jj*32;
            acc += s_depv[c] * row[c];
        }
        #pragma unroll
        for (int o = 16; o; o >>= 1) acc += __shfl_xor_sync(0xffffffffu, acc, o);
        if (tx == 0) s_hsim[h] = acc * invd * TEMP_INV;
    }
    __syncthreads();
    if (tid == 0) {
        float m = -1e30f;
        for (int h = 0; h < NHARD; h++) m = fmaxf(m, s_hsim[h]);
        float se = 0.0f;
        for (int h = 0; h < NHARD; h++) se += expf(s_hsim[h] - m);
        g_lse_hard[b*NPOS + p] = m + logf(se);
        g_max_hard[b*NPOS + p] = m;
    }
}

// ---------------- kernel 4: loss/accuracy reduction ---------------------------
__global__ __launch_bounds__(256) void k_loss(const float* __restrict__ valid) {
    __shared__ float sA[8], sB[8], sC[8];
    const int g = blockIdx.x * 256 + threadIdx.x;
    const int b = g >> 14;
    const int n = g & (NN-1);
    const int vq = n >> 7;
    const int u  = n & 127;

    float lse = g_lse[g];
    float pos = g_pos[g];
    float mx  = g_maxneg[g];
    if (((vq & 7) == 0) && ((u & 7) == 0)) {
        int p = (vq >> 3) * 16 + (u >> 3);
        float lh = g_lse_hard[b*NPOS + p];
        float mh = g_max_hard[b*NPOS + p];
        float m = fmaxf(lse, lh);
        lse = m + logf(expf(lse - m) + expf(lh - m));
        mx = fmaxf(mx, mh);
    }
    float mask = valid[g];
    float lossp = (lse - pos) * mask;
    float corr = (pos > mx && mask > 0.5f) ? 1.0f : 0.0f;
    float mk = mask;

    #pragma unroll
    for (int o = 16; o; o >>= 1) {
        lossp += __shfl_xor_sync(0xffffffffu, lossp, o);
        mk    += __shfl_xor_sync(0xffffffffu, mk,    o);
        corr  += __shfl_xor_sync(0xffffffffu, corr,  o);
    }
    if ((threadIdx.x & 31) == 0) {
        sA[threadIdx.x >> 5] = lossp;
        sB[threadIdx.x >> 5] = mk;
        sC[threadIdx.x >> 5] = corr;
    }
    __syncthreads();
    if (threadIdx.x == 0) {
        float a = 0.f, bb2 = 0.f, c2 = 0.f;
        #pragma unroll
        for (int j = 0; j < 8; j++) { a += sA[j]; bb2 += sB[j]; c2 += sC[j]; }
        atomicAdd(&g_acc[0], a);
        atomicAdd(&g_acc[1], bb2);
        atomicAdd(&g_acc[2], c2);
    }
}

// ---------------- kernel 5: epilogue ------------------------------------------
__global__ void k_out(float* out) {
    float denom = fmaxf(g_acc[1], 1.0f);
    out[0] = g_acc[0] / denom;
    out[1] = g_acc[2] / denom * 100.0f;
}

// ---------------- launch -------------------------------------------------------
extern "C" void kernel_launch(void* const* d_in, const int* in_sizes, int n_in,
                              void* d_out, int out_size) {
    const float* rgb   = (const float*)d_in[0];
    const float* dep   = (const float*)d_in[1];
    const float* proj  = (const float*)d_in[2];
    const float* valid = (const float*)d_in[3];
    const int*   ridx  = (const int*)d_in[4];
    const int*   offu  = (const int*)d_in[5];
    const int*   offv  = (const int*)d_in[6];
    float* out = (float*)d_out;

    const int smem_main = (CC*33 + NRAND*CC + 32*33 + 32 + 32 + 8*33) * (int)sizeof(float);
    cudaFuncSetAttribute(k_main, cudaFuncAttributeMaxDynamicSharedMemorySize, smem_main);

    k_init<<<1, 32>>>();
    k_norm_t<<<BB*NN/32, 256>>>(rgb);
    k_main<<<BB*NN/32, 256, smem_main>>>(dep, proj, ridx);
    k_hard<<<BB*NPOS, 256>>>(dep, proj, offu, offv);
    k_loss<<<BB*NN/256, 256>>>(valid);
    k_out<<<1, 1>>>(out);
}